// round 15
// baseline (speedup 1.0000x reference)
#include <cuda_runtime.h>

#define B_    64
#define S_    512
#define DIN_  512
#define DH_   1024
#define NCTA_RNN 128
#define RNN_THREADS 512
// smem: Wh padded [1024][36] (144KB) + h quads [4][1024] f4 (64KB) + redu (16KB) + 16 mbars
#define WS_BYTES   (1024 * 36 * 4)
#define HS_OFF     WS_BYTES
#define REDU_OFF   (HS_OFF + 65536)
#define MBAR_OFF   (REDU_OFF + 16384)
#define RNN_SMEM   (MBAR_OFF + 128)

// fine-grained producer counters: [bg][kslice-group], padded to 128B lines
__device__ unsigned g_cnt[4][8][32];
// cumulative read-done counter per bg (buffer-reuse guard), padded
__device__ unsigned g_rdone[4][32];
// ping-pong h: [phase][bg][quad][k] float4 (quad = 4 batches)
__device__ __align__(16) float4 g_h[2][4][4][DH_];

// ---------------- packed f32x2 helpers (FFMA2 on sm_103a) ----------------
static __device__ __forceinline__ unsigned long long pack2(float x, float y) {
    unsigned long long r;
    asm("mov.b64 %0, {%1, %2};" : "=l"(r) : "f"(x), "f"(y));
    return r;
}
static __device__ __forceinline__ void unpack2(unsigned long long v, float &x, float &y) {
    asm("mov.b64 {%0, %1}, %2;" : "=f"(x), "=f"(y) : "l"(v));
}
static __device__ __forceinline__ unsigned long long ffma2(unsigned long long a,
                                                           unsigned long long b,
                                                           unsigned long long c) {
    unsigned long long d;
    asm("fma.rn.f32x2 %0, %1, %2, %3;" : "=l"(d) : "l"(a), "l"(b), "l"(c));
    return d;
}
static __device__ __forceinline__ unsigned long long add2(unsigned long long a,
                                                          unsigned long long b) {
    unsigned long long d;
    asm("add.rn.f32x2 %0, %1, %2;" : "=l"(d) : "l"(a), "l"(b));
    return d;
}
static __device__ __forceinline__ unsigned long long shfl_xor64(unsigned long long v, int m) {
    unsigned lo = (unsigned)v, hi = (unsigned)(v >> 32);
    lo = __shfl_xor_sync(0xffffffffu, lo, m);
    hi = __shfl_xor_sync(0xffffffffu, hi, m);
    return ((unsigned long long)hi << 32) | (unsigned long long)lo;
}

static __device__ __forceinline__ float fast_tanh(float x) {
    float xc = fminf(fmaxf(x, -15.f), 15.f);
    float e = __expf(2.f * xc);
    return 1.f - __fdividef(2.f, e + 1.f);
}

static __device__ __forceinline__ unsigned smem_u32(const void* p) {
    unsigned r;
    asm("{ .reg .u64 t; cvta.to.shared.u64 t, %1; cvt.u32.u64 %0, t; }" : "=r"(r) : "l"(p));
    return r;
}

static __device__ __forceinline__ void poll_ge(const unsigned* addr, unsigned tgt) {
    unsigned long long a = (unsigned long long)addr;
    unsigned v;
    do {
        asm volatile("ld.acquire.gpu.u32 %0, [%1];" : "=r"(v) : "l"(a) : "memory");
    } while (v < tgt);
}

static __device__ __forceinline__ void rel_add(unsigned* addr) {
    asm volatile("red.release.gpu.add.u32 [%0], 1;"
                 :: "l"((unsigned long long)addr) : "memory");
}

static __device__ __forceinline__ void mbar_wait(unsigned mb, unsigned ph) {
    unsigned done;
    asm volatile(
        "{\n\t.reg .pred p;\n\t"
        "mbarrier.try_wait.parity.acquire.cta.shared::cta.b64 p, [%1], %2;\n\t"
        "selp.b32 %0, 1, 0, p;\n\t}"
        : "=r"(done) : "r"(mb), "r"(ph) : "memory");
    if (!done) {
        asm volatile(
            "{\n\t.reg .pred P1;\n\t"
            "WL_%=:\n\t"
            "mbarrier.try_wait.parity.acquire.cta.shared::cta.b64 P1, [%0], %1, 0x989680;\n\t"
            "@P1 bra.uni WD_%=;\n\t"
            "bra.uni WL_%=;\n\t"
            "WD_%=:\n\t}"
            :: "r"(mb), "r"(ph) : "memory");
    }
}

// ---------------- Kernel 1: xproj = x @ Wx + b (register double-buffered) ----------------
__global__ __launch_bounds__(256) void xproj_kernel(
    const float* __restrict__ X,
    const float* __restrict__ W,      // full (1536,1024); Wx = rows [0,512)
    const float* __restrict__ bias,
    float* __restrict__ C)            // (32768, 1024) = outs region
{
    __shared__ __align__(16) float As[16][132];
    __shared__ __align__(16) float Bs[16][64];

    const int tid = threadIdx.x;
    const int m0 = blockIdx.y * 128;
    const int n0 = blockIdx.x * 64;
    const int tx = tid & 15;
    const int ty = tid >> 4;
    const int ar = tid >> 2;
    const int ac = (tid & 3) << 2;
    const int br = tid >> 4;
    const int bc = (tid & 15) << 2;

    unsigned long long acc[4][4];
#pragma unroll
    for (int i = 0; i < 4; ++i)
#pragma unroll
        for (int jj = 0; jj < 4; ++jj) acc[i][jj] = 0ull;

    float4 a0 = *(const float4*)(X + (size_t)(m0 + ar) * DIN_ + ac);
    float4 a1 = *(const float4*)(X + (size_t)(m0 + ar + 64) * DIN_ + ac);
    float4 bv = *(const float4*)(W + (size_t)br * DH_ + n0 + bc);

    for (int kt = 0; kt < DIN_; kt += 16) {
        As[ac + 0][ar] = a0.x; As[ac + 1][ar] = a0.y;
        As[ac + 2][ar] = a0.z; As[ac + 3][ar] = a0.w;
        As[ac + 0][ar + 64] = a1.x; As[ac + 1][ar + 64] = a1.y;
        As[ac + 2][ar + 64] = a1.z; As[ac + 3][ar + 64] = a1.w;
        *(float4*)&Bs[br][bc] = bv;
        __syncthreads();

        if (kt + 16 < DIN_) {
            a0 = *(const float4*)(X + (size_t)(m0 + ar) * DIN_ + kt + 16 + ac);
            a1 = *(const float4*)(X + (size_t)(m0 + ar + 64) * DIN_ + kt + 16 + ac);
            bv = *(const float4*)(W + (size_t)(kt + 16 + br) * DH_ + n0 + bc);
        }

#pragma unroll
        for (int k = 0; k < 16; ++k) {
            const unsigned long long* ap =
                (const unsigned long long*)&As[k][ty << 3];
            ulonglong2 av0 = *(const ulonglong2*)(ap);
            ulonglong2 av1 = *(const ulonglong2*)(ap + 2);
            unsigned long long a2[4] = { av0.x, av0.y, av1.x, av1.y };
            float4 bq = *(const float4*)&Bs[k][tx << 2];
            unsigned long long b2[4] = { pack2(bq.x, bq.x), pack2(bq.y, bq.y),
                                         pack2(bq.z, bq.z), pack2(bq.w, bq.w) };
#pragma unroll
            for (int i = 0; i < 4; ++i)
#pragma unroll
                for (int jj = 0; jj < 4; ++jj)
                    acc[i][jj] = ffma2(a2[i], b2[jj], acc[i][jj]);
        }
        __syncthreads();
    }

    float4 bias4 = *(const float4*)(bias + n0 + (tx << 2));
#pragma unroll
    for (int i = 0; i < 4; ++i) {
        float l0, h0, l1, h1, l2, h2, l3, h3;
        unpack2(acc[i][0], l0, h0);
        unpack2(acc[i][1], l1, h1);
        unpack2(acc[i][2], l2, h2);
        unpack2(acc[i][3], l3, h3);
        int m = m0 + (ty << 3) + (i << 1);
        float4 v0 = make_float4(l0 + bias4.x, l1 + bias4.y, l2 + bias4.z, l3 + bias4.w);
        float4 v1 = make_float4(h0 + bias4.x, h1 + bias4.y, h2 + bias4.z, h3 + bias4.w);
        *(float4*)(C + (size_t)m * DH_ + n0 + (tx << 2)) = v0;
        *(float4*)(C + (size_t)(m + 1) * DH_ + n0 + (tx << 2)) = v1;
    }
}

// ---------------- counter reset (runs before recurrence every launch) ----------------
__global__ void reset_kernel() {
    int i = threadIdx.x;
    if (i < 32) g_cnt[i >> 3][i & 7][0] = 0u;
    if (i < 4)  g_rdone[i][0] = 0u;
}

// ---------------- Kernel 2: persistent recurrence, fine-grained dataflow ----------------
// 128 CTAs = 32 cg x 4 bg. Warp (ksl,bpg): k-slice 128, 8 batches.
// Warp ksl's h slice is produced by exactly 4 CTAs (cg = 4ksl..4ksl+3, same bg):
// per-warp counter poll -> per-warp 2x2KB bulk copy -> GEMV. No grid barrier.
__global__ __launch_bounds__(RNN_THREADS, 1)
void rnn_kernel(
    const float* __restrict__ h0,
    const float* __restrict__ W,      // Wh = rows [512, 1536)
    float* __restrict__ out,          // (B,S,DH): xp in, h out (in place)
    float* __restrict__ hlast)        // (B, DH)
{
    extern __shared__ unsigned char sraw[];
    float*  ws   = (float*)sraw;                         // [1024][36] padded Wh slice
    float4* hsq  = (float4*)(sraw + HS_OFF);             // [4 quads][1024 k]
    unsigned long long* redu =
        (unsigned long long*)(sraw + REDU_OFF);          // [8 ksl][2 bpg][32 col][4 u]
    const unsigned mbar_u32 = smem_u32(sraw + MBAR_OFF); // 16 mbarriers
    const unsigned hs_u32 = smem_u32(hsq);

    const int tid = threadIdx.x;
    const int cg = blockIdx.x & 31;       // col group 0..31
    const int bg = blockIdx.x >> 5;       // batch group 0..3
    const int lane = tid & 31;
    const int wid = tid >> 5;
    const int ksl = wid & 7;              // k-slice 0..7 (128 k)
    const int bpg = wid >> 3;             // batch-pair group 0/1 (8 batches)
    const int cp = lane & 3;              // col base = 8*cp
    const int kpos = lane >> 2;           // 0..7

    // epilogue mapping (threads 0..255)
    const int ecol = tid & 31;
    const int ebp = tid >> 5;             // 0..7
    const int ebpg = ebp >> 2;
    const int eu = ebp & 3;
    const int jo = (cg << 5) + ecol;
    const int eq = (ebpg << 1) + (eu >> 1);            // quad 0..3
    const int b0 = (bg << 4) + (eq << 2) + ((eu & 1) << 1);

    if (tid < 16) {
        asm volatile("mbarrier.init.shared.b64 [%0], 1;"
                     :: "r"(mbar_u32 + (unsigned)tid * 8u) : "memory");
    }

    // ---- one-time: stage Wh slice (1024 x 32) into padded [k][36] smem ----
    {
        const float* wsrc = W + (size_t)DIN_ * DH_ + (cg << 5);
        for (int idx = tid; idx < (1024 * 32) / 4; idx += RNN_THREADS) {
            int r = idx >> 3;
            int c = (idx & 7) << 2;
            float4 v = *(const float4*)(wsrc + (size_t)r * DH_ + c);
            *(float4*)(ws + r * 36 + c) = v;
        }
    }

    // ---- prefetch xp for t=0 ----
    float xpc0 = 0.f, xpc1 = 0.f;
    size_t i0 = 0, i1 = 0;
    if (tid < 256) {
        i0 = ((size_t)b0 * S_) * DH_ + jo;
        i1 = i0 + (size_t)S_ * DH_;
        xpc0 = out[i0];
        xpc1 = out[i1];
    }

    // ---- t=0 staging: hsq[q][k] from h0 ----
    for (int idx = tid; idx < 4096; idx += RNN_THREADS) {
        int q = idx >> 10;
        int k = idx & 1023;
        const float* hb = h0 + (size_t)((bg << 4) + (q << 2)) * DH_ + k;
        hsq[idx] = make_float4(hb[0], hb[DH_], hb[2 * DH_], hb[3 * DH_]);
    }
    __syncthreads();

    for (int t = 0; t < S_; ++t) {
        // ---- prefetch xp for t+1 (issue early, overlaps poll/copy) ----
        float xpn0 = 0.f, xpn1 = 0.f;
        if (tid < 256 && t + 1 < S_) {
            xpn0 = out[i0 + DH_];
            xpn1 = out[i1 + DH_];
        }

        // ---- per-warp: wait for 4 producers, fetch own 2x2KB h slice ----
        if (t > 0) {
            poll_ge(&g_cnt[bg][ksl][0], 4u * (unsigned)t);
            const unsigned mb = mbar_u32 + (unsigned)wid * 8u;
            if (lane == 0) {
                asm volatile("fence.proxy.async.shared::cta;" ::: "memory");
                asm volatile("mbarrier.arrive.expect_tx.shared.b64 _, [%0], %1;"
                             :: "r"(mb), "r"(4096u) : "memory");
                const float4* s0 = &g_h[(t - 1) & 1][bg][bpg << 1][0] + (ksl << 7);
                const float4* s1 = s0 + 1024;
                const unsigned off = (unsigned)((((bpg << 1) << 10) + (ksl << 7)) << 4);
                asm volatile("cp.async.bulk.shared::cta.global.mbarrier::complete_tx::bytes "
                             "[%0], [%1], %2, [%3];"
                             :: "r"(hs_u32 + off), "l"(s0), "r"(2048u), "r"(mb) : "memory");
                asm volatile("cp.async.bulk.shared::cta.global.mbarrier::complete_tx::bytes "
                             "[%0], [%1], %2, [%3];"
                             :: "r"(hs_u32 + off + (1024u << 4)), "l"(s1), "r"(2048u), "r"(mb) : "memory");
            }
            mbar_wait(mb, (unsigned)((t - 1) & 1));
        }

        // ---- GEMV: 8 cols x 8 batches x 16 k per thread (warp-private hsq slice) ----
        unsigned long long acc[32];   // [c 0..7][u 0..3]
#pragma unroll
        for (int a = 0; a < 32; ++a) acc[a] = 0ull;

        {
            const int kbase = (ksl << 7) + kpos;
            const float* wrow = ws + kbase * 36 + (cp << 3);
            const ulonglong2* hA = (const ulonglong2*)hsq + ((bpg << 1) << 10) + kbase;
            const ulonglong2* hB = hA + 1024;
#pragma unroll
            for (int i = 0; i < 16; ++i) {
                ulonglong2 ha = hA[i << 3];
                ulonglong2 hb2 = hB[i << 3];
#pragma unroll
                for (int half = 0; half < 2; ++half) {
                    float4 wv = *(const float4*)(wrow + (i * 36 * 8) + (half << 2));
#pragma unroll
                    for (int c2 = 0; c2 < 4; ++c2) {
                        float wf = (c2 == 0) ? wv.x : (c2 == 1) ? wv.y : (c2 == 2) ? wv.z : wv.w;
                        unsigned long long wp = pack2(wf, wf);
                        const int c = (half << 2) + c2;
                        acc[c * 4 + 0] = ffma2(ha.x, wp, acc[c * 4 + 0]);
                        acc[c * 4 + 1] = ffma2(ha.y, wp, acc[c * 4 + 1]);
                        acc[c * 4 + 2] = ffma2(hb2.x, wp, acc[c * 4 + 2]);
                        acc[c * 4 + 3] = ffma2(hb2.y, wp, acc[c * 4 + 3]);
                    }
                }
            }
        }

        // ---- reduce-scatter over kpos (masks 16,8,4) ----
#pragma unroll
        for (int j = 0; j < 16; ++j) {
            bool bit = (lane & 16) != 0;
            unsigned long long send = bit ? acc[j] : acc[j + 16];
            unsigned long long recv = shfl_xor64(send, 16);
            unsigned long long keep = bit ? acc[j + 16] : acc[j];
            acc[j] = add2(keep, recv);
        }
#pragma unroll
        for (int j = 0; j < 8; ++j) {
            bool bit = (lane & 8) != 0;
            unsigned long long send = bit ? acc[j] : acc[j + 8];
            unsigned long long recv = shfl_xor64(send, 8);
            unsigned long long keep = bit ? acc[j + 8] : acc[j];
            acc[j] = add2(keep, recv);
        }
#pragma unroll
        for (int j = 0; j < 4; ++j) {
            bool bit = (lane & 4) != 0;
            unsigned long long send = bit ? acc[j] : acc[j + 4];
            unsigned long long recv = shfl_xor64(send, 4);
            unsigned long long keep = bit ? acc[j + 4] : acc[j];
            acc[j] = add2(keep, recv);
        }

        // ---- write per-kslice partials: redu[ksl][bpg][col][u] ----
        {
            const int col = (cp << 3) + kpos;
            const int base = (((ksl << 1) + bpg) << 5) + col;
            ulonglong2 v0; v0.x = acc[0]; v0.y = acc[1];
            ulonglong2 v1; v1.x = acc[2]; v1.y = acc[3];
            *(ulonglong2*)&redu[base << 2] = v0;
            *(ulonglong2*)&redu[(base << 2) + 2] = v1;
        }

        // ---- buffer-reuse guard: warp 8 polls read-done of step t-1 (overlaps) ----
        if (wid == 8 && t >= 2)
            poll_ge(&g_rdone[bg][0], 32u * (unsigned)(t - 1));

        __syncthreads();   // #1: redu ready; all warps' copy-in done; guard passed

        // signal: this CTA finished reading buffer (t-1)&1 (its copy-in for step t)
        if (tid == 1 && t >= 1) rel_add(&g_rdone[bg][0]);

        // ---- epilogue: compute h, publish g_h ----
        float hv0 = 0.f, hv1 = 0.f;
        if (tid < 256) {
            const unsigned long long* rp = redu + ((ebpg << 5) + ecol) * 4 + eu;
            unsigned long long s = rp[0];
#pragma unroll
            for (int q = 1; q < 8; ++q) s = add2(s, rp[q << 8]);
            float sx, sy;
            unpack2(s, sx, sy);
            hv0 = fast_tanh(xpc0 + sx);
            hv1 = fast_tanh(xpc1 + sy);
            float2* dst = (float2*)((char*)&g_h[t & 1][bg][eq][jo] + ((eu & 1) << 3));
            *dst = make_float2(hv0, hv1);
            if (t == S_ - 1) {
                hlast[(size_t)b0 * DH_ + jo] = hv0;
                hlast[(size_t)(b0 + 1) * DH_ + jo] = hv1;
            }
        }

        __syncthreads();   // #2: g_h slice fully written (also orders redu reads vs next STS)

        // ---- publish: one release-add on this cg-group's counter ----
        if (tid == 0) rel_add(&g_cnt[bg][cg >> 2][0]);

        // ---- out[] stores off the critical path ----
        if (tid < 256) {
            out[i0] = hv0;
            out[i1] = hv1;
            i0 += DH_;
            i1 += DH_;
        }
        xpc0 = xpn0;
        xpc1 = xpn1;
    }
}

// ---------------- launch ----------------
extern "C" void kernel_launch(void* const* d_in, const int* in_sizes, int n_in,
                              void* d_out, int out_size) {
    (void)in_sizes; (void)n_in; (void)out_size;
    const float* x  = (const float*)d_in[0];
    const float* h0 = (const float*)d_in[1];
    const float* W  = (const float*)d_in[2];
    const float* b  = (const float*)d_in[3];
    float* out = (float*)d_out;                       // (B,S,DH) outs
    float* hlast = out + (size_t)B_ * S_ * DH_;       // (B,DH) h_last

    cudaFuncSetAttribute(rnn_kernel, cudaFuncAttributeMaxDynamicSharedMemorySize, RNN_SMEM);

    dim3 g1(DH_ / 64, (B_ * S_) / 128);
    xproj_kernel<<<g1, 256>>>(x, W, b, out);
    reset_kernel<<<1, 32>>>();
    rnn_kernel<<<NCTA_RNN, RNN_THREADS, RNN_SMEM>>>(h0, W, out, hlast);
}

// round 16
// speedup vs baseline: 1.0623x; 1.0623x over previous
#include <cuda_runtime.h>

#define B_    64
#define S_    512
#define DIN_  512
#define DH_   1024
#define NCTA_RNN 128
#define RNN_THREADS 512
// smem: Wh padded [1024][36] (144KB) + h quads [4][1024] f4 (64KB) + redu (16KB) + mbars
#define WS_BYTES   (1024 * 36 * 4)
#define HS_OFF     WS_BYTES
#define REDU_OFF   (HS_OFF + 65536)
#define MBAR_OFF   (REDU_OFF + 16384)
#define RNN_SMEM   (MBAR_OFF + 64)

__device__ unsigned g_bars[4][32];                 // per-batch-group barrier
// ping-pong h: [phase][bg][quad][k] float4 (quad = 4 batches); per-bg slice = 64KB contiguous
__device__ __align__(16) float4 g_h[2][4][4][DH_];

// ---------------- packed f32x2 helpers (FFMA2 on sm_103a) ----------------
static __device__ __forceinline__ unsigned long long pack2(float x, float y) {
    unsigned long long r;
    asm("mov.b64 %0, {%1, %2};" : "=l"(r) : "f"(x), "f"(y));
    return r;
}
static __device__ __forceinline__ void unpack2(unsigned long long v, float &x, float &y) {
    asm("mov.b64 {%0, %1}, %2;" : "=f"(x), "=f"(y) : "l"(v));
}
static __device__ __forceinline__ unsigned long long ffma2(unsigned long long a,
                                                           unsigned long long b,
                                                           unsigned long long c) {
    unsigned long long d;
    asm("fma.rn.f32x2 %0, %1, %2, %3;" : "=l"(d) : "l"(a), "l"(b), "l"(c));
    return d;
}
static __device__ __forceinline__ unsigned long long add2(unsigned long long a,
                                                          unsigned long long b) {
    unsigned long long d;
    asm("add.rn.f32x2 %0, %1, %2;" : "=l"(d) : "l"(a), "l"(b));
    return d;
}
static __device__ __forceinline__ unsigned long long shfl_xor64(unsigned long long v, int m) {
    unsigned lo = (unsigned)v, hi = (unsigned)(v >> 32);
    lo = __shfl_xor_sync(0xffffffffu, lo, m);
    hi = __shfl_xor_sync(0xffffffffu, hi, m);
    return ((unsigned long long)hi << 32) | (unsigned long long)lo;
}

static __device__ __forceinline__ float fast_tanh(float x) {
    float xc = fminf(fmaxf(x, -15.f), 15.f);
    float e = __expf(2.f * xc);
    return 1.f - __fdividef(2.f, e + 1.f);
}

static __device__ __forceinline__ unsigned smem_u32(const void* p) {
    unsigned r;
    asm("{ .reg .u64 t; cvta.to.shared.u64 t, %1; cvt.u32.u64 %0, t; }" : "=r"(r) : "l"(p));
    return r;
}

static __device__ __forceinline__ unsigned cluster_rank() {
    unsigned r;
    asm("mov.u32 %0, %%cluster_ctarank;" : "=r"(r));
    return r;
}

static __device__ __forceinline__ void mbar_wait(unsigned mb, unsigned ph) {
    unsigned done;
    asm volatile(
        "{\n\t.reg .pred p;\n\t"
        "mbarrier.try_wait.parity.acquire.cta.shared::cta.b64 p, [%1], %2;\n\t"
        "selp.b32 %0, 1, 0, p;\n\t}"
        : "=r"(done) : "r"(mb), "r"(ph) : "memory");
    if (!done) {
        asm volatile(
            "{\n\t.reg .pred P1;\n\t"
            "WL_%=:\n\t"
            "mbarrier.try_wait.parity.acquire.cta.shared::cta.b64 P1, [%0], %1, 0x989680;\n\t"
            "@P1 bra.uni WD_%=;\n\t"
            "bra.uni WL_%=;\n\t"
            "WD_%=:\n\t}"
            :: "r"(mb), "r"(ph) : "memory");
    }
}

// ---------------- Kernel 1: xproj = x @ Wx + b (register double-buffered) ----------------
__global__ __launch_bounds__(256) void xproj_kernel(
    const float* __restrict__ X,
    const float* __restrict__ W,      // full (1536,1024); Wx = rows [0,512)
    const float* __restrict__ bias,
    float* __restrict__ C)            // (32768, 1024) = outs region
{
    __shared__ __align__(16) float As[16][132];
    __shared__ __align__(16) float Bs[16][64];

    const int tid = threadIdx.x;
    const int m0 = blockIdx.y * 128;
    const int n0 = blockIdx.x * 64;
    const int tx = tid & 15;
    const int ty = tid >> 4;
    const int ar = tid >> 2;
    const int ac = (tid & 3) << 2;
    const int br = tid >> 4;
    const int bc = (tid & 15) << 2;

    unsigned long long acc[4][4];
#pragma unroll
    for (int i = 0; i < 4; ++i)
#pragma unroll
        for (int jj = 0; jj < 4; ++jj) acc[i][jj] = 0ull;

    float4 a0 = *(const float4*)(X + (size_t)(m0 + ar) * DIN_ + ac);
    float4 a1 = *(const float4*)(X + (size_t)(m0 + ar + 64) * DIN_ + ac);
    float4 bv = *(const float4*)(W + (size_t)br * DH_ + n0 + bc);

    for (int kt = 0; kt < DIN_; kt += 16) {
        As[ac + 0][ar] = a0.x; As[ac + 1][ar] = a0.y;
        As[ac + 2][ar] = a0.z; As[ac + 3][ar] = a0.w;
        As[ac + 0][ar + 64] = a1.x; As[ac + 1][ar + 64] = a1.y;
        As[ac + 2][ar + 64] = a1.z; As[ac + 3][ar + 64] = a1.w;
        *(float4*)&Bs[br][bc] = bv;
        __syncthreads();

        if (kt + 16 < DIN_) {
            a0 = *(const float4*)(X + (size_t)(m0 + ar) * DIN_ + kt + 16 + ac);
            a1 = *(const float4*)(X + (size_t)(m0 + ar + 64) * DIN_ + kt + 16 + ac);
            bv = *(const float4*)(W + (size_t)(kt + 16 + br) * DH_ + n0 + bc);
        }

#pragma unroll
        for (int k = 0; k < 16; ++k) {
            const unsigned long long* ap =
                (const unsigned long long*)&As[k][ty << 3];
            ulonglong2 av0 = *(const ulonglong2*)(ap);
            ulonglong2 av1 = *(const ulonglong2*)(ap + 2);
            unsigned long long a2[4] = { av0.x, av0.y, av1.x, av1.y };
            float4 bq = *(const float4*)&Bs[k][tx << 2];
            unsigned long long b2[4] = { pack2(bq.x, bq.x), pack2(bq.y, bq.y),
                                         pack2(bq.z, bq.z), pack2(bq.w, bq.w) };
#pragma unroll
            for (int i = 0; i < 4; ++i)
#pragma unroll
                for (int jj = 0; jj < 4; ++jj)
                    acc[i][jj] = ffma2(a2[i], b2[jj], acc[i][jj]);
        }
        __syncthreads();
    }

    float4 bias4 = *(const float4*)(bias + n0 + (tx << 2));
#pragma unroll
    for (int i = 0; i < 4; ++i) {
        float l0, h0, l1, h1, l2, h2, l3, h3;
        unpack2(acc[i][0], l0, h0);
        unpack2(acc[i][1], l1, h1);
        unpack2(acc[i][2], l2, h2);
        unpack2(acc[i][3], l3, h3);
        int m = m0 + (ty << 3) + (i << 1);
        float4 v0 = make_float4(l0 + bias4.x, l1 + bias4.y, l2 + bias4.z, l3 + bias4.w);
        float4 v1 = make_float4(h0 + bias4.x, h1 + bias4.y, h2 + bias4.z, h3 + bias4.w);
        *(float4*)(C + (size_t)m * DH_ + n0 + (tx << 2)) = v0;
        *(float4*)(C + (size_t)(m + 1) * DH_ + n0 + (tx << 2)) = v1;
    }
}

// ---------------- barrier reset ----------------
__global__ void reset_kernel() {
    if (threadIdx.x < 4) g_bars[threadIdx.x][0] = 0u;
}

// ---------------- Kernel 2: persistent recurrence, 512 threads, 4-CTA clusters ----------------
// Multicast TMA split into 2 x 32KB chunks (quads 0-1 / 2-3); warps gated by bpg so
// half the warps start the GEMV as soon as their chunk lands.
__global__ __launch_bounds__(RNN_THREADS, 1) __cluster_dims__(4, 1, 1)
void rnn_kernel(
    const float* __restrict__ h0,
    const float* __restrict__ W,      // Wh = rows [512, 1536)
    float* __restrict__ out,          // (B,S,DH): xp in, h out (in place)
    float* __restrict__ hlast)        // (B, DH)
{
    extern __shared__ unsigned char sraw[];
    float*  ws   = (float*)sraw;                         // [1024][36] padded Wh slice
    float4* hsq  = (float4*)(sraw + HS_OFF);             // [4 quads][1024 k]
    unsigned long long* redu =
        (unsigned long long*)(sraw + REDU_OFF);          // [8 ksl][2 bpg][32 col][4 u]
    const unsigned mbar_u32 = smem_u32(sraw + MBAR_OFF); // 2 mbarriers
    const unsigned hs_u32 = smem_u32(hsq);

    const int tid = threadIdx.x;
    const int cg = blockIdx.x & 31;       // col group 0..31
    const int bg = blockIdx.x >> 5;       // batch group 0..3
    const unsigned crank = cluster_rank();
    const int lane = tid & 31;
    const int wid = tid >> 5;
    const int ksl = wid & 7;              // k-slice 0..7 (128 k)
    const int bpg = wid >> 3;             // batch-pair group 0/1 (8 batches)
    const int cp = lane & 3;              // col base = 8*cp
    const int kpos = lane >> 2;           // 0..7

    // epilogue mapping (threads 0..255)
    const int ecol = tid & 31;
    const int ebp = tid >> 5;             // 0..7
    const int ebpg = ebp >> 2;
    const int eu = ebp & 3;
    const int jo = (cg << 5) + ecol;
    const int eq = (ebpg << 1) + (eu >> 1);            // quad 0..3
    const int b0 = (bg << 4) + (eq << 2) + ((eu & 1) << 1);

    volatile unsigned* bar = &g_bars[bg][0];

    if (tid < 2) {
        asm volatile("mbarrier.init.shared.b64 [%0], 1;"
                     :: "r"(mbar_u32 + (unsigned)tid * 8u) : "memory");
    }

    // ---- one-time: stage Wh slice (1024 x 32) into padded [k][36] smem ----
    {
        const float* wsrc = W + (size_t)DIN_ * DH_ + (cg << 5);
        for (int idx = tid; idx < (1024 * 32) / 4; idx += RNN_THREADS) {
            int r = idx >> 3;
            int c = (idx & 7) << 2;
            float4 v = *(const float4*)(wsrc + (size_t)r * DH_ + c);
            *(float4*)(ws + r * 36 + c) = v;
        }
    }

    // ---- prefetch xp for t=0 ----
    float xpc0 = 0.f, xpc1 = 0.f;
    size_t i0 = 0, i1 = 0;
    if (tid < 256) {
        i0 = ((size_t)b0 * S_) * DH_ + jo;
        i1 = i0 + (size_t)S_ * DH_;
        xpc0 = out[i0];
        xpc1 = out[i1];
    }

    // ---- t=0 staging: hsq[q][k] from h0 ----
    for (int idx = tid; idx < 4096; idx += RNN_THREADS) {
        int q = idx >> 10;
        int k = idx & 1023;
        const float* hb = h0 + (size_t)((bg << 4) + (q << 2)) * DH_ + k;
        hsq[idx] = make_float4(hb[0], hb[DH_], hb[2 * DH_], hb[3 * DH_]);
    }
    __syncthreads();

    // cluster-wide: mbarriers initialized in all CTAs before any multicast lands
    asm volatile("barrier.cluster.arrive.aligned;" ::: "memory");
    asm volatile("barrier.cluster.wait.aligned;" ::: "memory");

    int ph = 0;

    for (int t = 0; t < S_; ++t) {
        // ---- stage h_prev via TWO 32KB multicast chunks per cluster (t>=1) ----
        if (t > 0 && tid == 0) {
            asm volatile("fence.proxy.async.shared::cta;" ::: "memory");
            asm volatile("mbarrier.arrive.expect_tx.shared.b64 _, [%0], %1;"
                         :: "r"(mbar_u32), "r"(32768u) : "memory");
            asm volatile("mbarrier.arrive.expect_tx.shared.b64 _, [%0], %1;"
                         :: "r"(mbar_u32 + 8u), "r"(32768u) : "memory");
            if (crank == 0) {
                const char* src = (const char*)&g_h[(t - 1) & 1][bg][0][0];
                asm volatile(
                    "cp.async.bulk.shared::cluster.global.mbarrier::complete_tx::bytes.multicast::cluster "
                    "[%0], [%1], %2, [%3], %4;"
                    :: "r"(hs_u32), "l"(src), "r"(32768u), "r"(mbar_u32),
                       "h"((unsigned short)0xFu) : "memory");
                asm volatile(
                    "cp.async.bulk.shared::cluster.global.mbarrier::complete_tx::bytes.multicast::cluster "
                    "[%0], [%1], %2, [%3], %4;"
                    :: "r"(hs_u32 + 32768u), "l"(src + 32768), "r"(32768u), "r"(mbar_u32 + 8u),
                       "h"((unsigned short)0xFu) : "memory");
            }
        }

        // ---- prefetch xp for t+1 (overlaps TMA) ----
        float xpn0 = 0.f, xpn1 = 0.f;
        if (tid < 256 && t + 1 < S_) {
            xpn0 = out[i0 + DH_];
            xpn1 = out[i1 + DH_];
        }

        // ---- each warp waits only its own 32KB chunk (bpg) ----
        if (t > 0) {
            mbar_wait(mbar_u32 + (unsigned)(bpg << 3), (unsigned)ph);
            ph ^= 1;
        }

        // ---- GEMV: 8 cols x 8 batches x 16 k per thread ----
        unsigned long long acc[32];   // [c 0..7][u 0..3], flat c*4+u
#pragma unroll
        for (int a = 0; a < 32; ++a) acc[a] = 0ull;

        {
            const int kbase = (ksl << 7) + kpos;
            const float* wrow = ws + kbase * 36 + (cp << 3);
            const ulonglong2* hA = (const ulonglong2*)hsq + ((bpg << 1) << 10) + kbase;
            const ulonglong2* hB = hA + 1024;
#pragma unroll
            for (int i = 0; i < 16; ++i) {
                ulonglong2 ha = hA[i << 3];        // quad 2bpg @ k
                ulonglong2 hb2 = hB[i << 3];       // quad 2bpg+1 @ k
#pragma unroll
                for (int half = 0; half < 2; ++half) {
                    float4 wv = *(const float4*)(wrow + (i * 36 * 8) + (half << 2));
#pragma unroll
                    for (int c2 = 0; c2 < 4; ++c2) {
                        float wf = (c2 == 0) ? wv.x : (c2 == 1) ? wv.y : (c2 == 2) ? wv.z : wv.w;
                        unsigned long long wp = pack2(wf, wf);
                        const int c = (half << 2) + c2;
                        acc[c * 4 + 0] = ffma2(ha.x, wp, acc[c * 4 + 0]);
                        acc[c * 4 + 1] = ffma2(ha.y, wp, acc[c * 4 + 1]);
                        acc[c * 4 + 2] = ffma2(hb2.x, wp, acc[c * 4 + 2]);
                        acc[c * 4 + 3] = ffma2(hb2.y, wp, acc[c * 4 + 3]);
                    }
                }
            }
        }

        // ---- reduce-scatter over kpos (masks 16,8,4): lane ends with col cp*8+kpos ----
#pragma unroll
        for (int j = 0; j < 16; ++j) {
            bool bit = (lane & 16) != 0;
            unsigned long long send = bit ? acc[j] : acc[j + 16];
            unsigned long long recv = shfl_xor64(send, 16);
            unsigned long long keep = bit ? acc[j + 16] : acc[j];
            acc[j] = add2(keep, recv);
        }
#pragma unroll
        for (int j = 0; j < 8; ++j) {
            bool bit = (lane & 8) != 0;
            unsigned long long send = bit ? acc[j] : acc[j + 8];
            unsigned long long recv = shfl_xor64(send, 8);
            unsigned long long keep = bit ? acc[j + 8] : acc[j];
            acc[j] = add2(keep, recv);
        }
#pragma unroll
        for (int j = 0; j < 4; ++j) {
            bool bit = (lane & 4) != 0;
            unsigned long long send = bit ? acc[j] : acc[j + 4];
            unsigned long long recv = shfl_xor64(send, 4);
            unsigned long long keep = bit ? acc[j + 4] : acc[j];
            acc[j] = add2(keep, recv);
        }

        // ---- write per-kslice partials: redu[ksl][bpg][col][u] ----
        {
            const int col = (cp << 3) + kpos;
            const int base = (((ksl << 1) + bpg) << 5) + col;
            ulonglong2 v0; v0.x = acc[0]; v0.y = acc[1];
            ulonglong2 v1; v1.x = acc[2]; v1.y = acc[3];
            *(ulonglong2*)&redu[base << 2] = v0;
            *(ulonglong2*)&redu[(base << 2) + 2] = v1;
        }
        __syncthreads();

        // ---- epilogue: compute h, publish g_h FIRST (critical path), out later ----
        float hv0 = 0.f, hv1 = 0.f;
        if (tid < 256) {
            const unsigned long long* rp = redu + ((ebpg << 5) + ecol) * 4 + eu;
            unsigned long long s = rp[0];
#pragma unroll
            for (int q = 1; q < 8; ++q) s = add2(s, rp[q << 8]);
            float sx, sy;
            unpack2(s, sx, sy);
            hv0 = fast_tanh(xpc0 + sx);
            hv1 = fast_tanh(xpc1 + sy);
            float2* dst = (float2*)((char*)&g_h[t & 1][bg][eq][jo] + ((eu & 1) << 3));
            *dst = make_float2(hv0, hv1);
            if (t == S_ - 1) {
                hlast[(size_t)b0 * DH_ + jo] = hv0;
                hlast[(size_t)(b0 + 1) * DH_ + jo] = hv1;
            }
        }

        // ---- barrier release (publishes g_h), then overlap out[] stores with poll ----
        __syncthreads();
        if (tid == 0) {
            unsigned long long addr = (unsigned long long)bar;
            asm volatile("red.release.gpu.add.u32 [%0], 1;" :: "l"(addr) : "memory");
        }
        if (tid < 256) {
            out[i0] = hv0;
            out[i1] = hv1;
            i0 += DH_;
            i1 += DH_;
        }
        xpc0 = xpn0;
        xpc1 = xpn1;
        if (tid == 0) {
            unsigned long long addr = (unsigned long long)bar;
            const unsigned target = 32u * (unsigned)(t + 1);
            unsigned v;
            do {
                asm volatile("ld.acquire.gpu.u32 %0, [%1];" : "=r"(v) : "l"(addr) : "memory");
            } while (v < target);
        }
        __syncthreads();
    }

    // cluster-wide quiesce before exit
    asm volatile("barrier.cluster.arrive.aligned;" ::: "memory");
    asm volatile("barrier.cluster.wait.aligned;" ::: "memory");
}

// ---------------- launch ----------------
extern "C" void kernel_launch(void* const* d_in, const int* in_sizes, int n_in,
                              void* d_out, int out_size) {
    (void)in_sizes; (void)n_in; (void)out_size;
    const float* x  = (const float*)d_in[0];
    const float* h0 = (const float*)d_in[1];
    const float* W  = (const float*)d_in[2];
    const float* b  = (const float*)d_in[3];
    float* out = (float*)d_out;                       // (B,S,DH) outs
    float* hlast = out + (size_t)B_ * S_ * DH_;       // (B,DH) h_last

    cudaFuncSetAttribute(rnn_kernel, cudaFuncAttributeMaxDynamicSharedMemorySize, RNN_SMEM);

    dim3 g1(DH_ / 64, (B_ * S_) / 128);
    xproj_kernel<<<g1, 256>>>(x, W, b, out);
    reset_kernel<<<1, 32>>>();
    rnn_kernel<<<NCTA_RNN, RNN_THREADS, RNN_SMEM>>>(h0, W, out, hlast);
}